// round 1
// baseline (speedup 1.0000x reference)
#include <cuda_runtime.h>
#include <cstdint>

#define NN   32768
#define KNB  16
#define FD   128
#define PITCH 132          // floats per U row: (lane stride 4*132 words) ≡ 4 mod 32 banks -> conflict-free LDS.128
#define NEG  0.2f

// Device-global scratch (allowed; runtime alloc is not)
__device__ __align__(16) float g_U[2 * FD * PITCH];   // U[m][o][f], m=0:Wa1@W, m=1:Wa2@W
__device__ __align__(16) float g_nproj[NN * FD];      // nodes @ W^T

__device__ __forceinline__ void fma2(unsigned long long &d, unsigned long long a, unsigned long long b) {
    asm("fma.rn.f32x2 %0, %1, %2, %0;" : "+l"(d) : "l"(a), "l"(b));
}
__device__ __forceinline__ float hsum2(unsigned long long v) {
    float lo, hi;
    asm("mov.b64 {%0, %1}, %2;" : "=f"(lo), "=f"(hi) : "l"(v));
    return lo + hi;
}

// ---------------------------------------------------------------------------
// U[m][o][f] = sum_op Wa[o][m*128+op] * W[op][f]
// ---------------------------------------------------------------------------
__global__ void k_computeU(const float* __restrict__ W, const float* __restrict__ Wa) {
    int f = threadIdx.x;
    int o = blockIdx.x & 127;
    int m = blockIdx.x >> 7;
    float acc = 0.f;
#pragma unroll 8
    for (int op = 0; op < FD; ++op)
        acc += Wa[o * 256 + m * 128 + op] * W[op * FD + f];
    g_U[(m * FD + o) * PITCH + f] = acc;
}

// ---------------------------------------------------------------------------
// nproj[n][o] = sum_f nodes[n][f] * W[o][f]
// Each warp: 8 node rows x 128 outputs, f32x2-paired over f.
// ---------------------------------------------------------------------------
__global__ __launch_bounds__(256, 2) void k_nproj(const float* __restrict__ nodes,
                                                  const float* __restrict__ W) {
    extern __shared__ float sm[];
    float* sW = sm;                     // [128][PITCH]
    float* sRowBase = sm + FD * PITCH;  // [8 warps][8 rows][128]

    for (int i = threadIdx.x; i < FD * FD; i += 256)
        sW[(i >> 7) * PITCH + (i & 127)] = W[i];
    __syncthreads();

    const int warp = threadIdx.x >> 5, lane = threadIdx.x & 31;
    float* sR = sRowBase + warp * 8 * FD;
    const int base = (blockIdx.x * 8 + warp) * 8;
    if (base >= NN) return;

#pragma unroll
    for (int r = 0; r < 8; ++r) {
        float4 v = reinterpret_cast<const float4*>(nodes + (size_t)(base + r) * FD)[lane];
        reinterpret_cast<float4*>(sR + r * FD)[lane] = v;
    }
    __syncwarp();

    const ulonglong2* up[4];
#pragma unroll
    for (int j = 0; j < 4; ++j)
        up[j] = reinterpret_cast<const ulonglong2*>(sW + (lane + 32 * j) * PITCH);

    unsigned long long acc[8][4];
#pragma unroll
    for (int r = 0; r < 8; ++r)
#pragma unroll
        for (int j = 0; j < 4; ++j) acc[r][j] = 0ull;

#pragma unroll 4
    for (int k4 = 0; k4 < 32; ++k4) {
        ulonglong2 u[4];
#pragma unroll
        for (int j = 0; j < 4; ++j) u[j] = up[j][k4];
#pragma unroll
        for (int r = 0; r < 8; ++r) {
            ulonglong2 a = reinterpret_cast<const ulonglong2*>(sR + r * FD)[k4];
#pragma unroll
            for (int j = 0; j < 4; ++j) {
                fma2(acc[r][j], a.x, u[j].x);
                fma2(acc[r][j], a.y, u[j].y);
            }
        }
    }

#pragma unroll
    for (int r = 0; r < 8; ++r)
#pragma unroll
        for (int j = 0; j < 4; ++j)
            g_nproj[(size_t)(base + r) * FD + lane + 32 * j] = hsum2(acc[r][j]);
}

// ---------------------------------------------------------------------------
// Main fused kernel: per edge e of node n:
//   nap = neighbors[e]@U1^T + aspects[e]@U2^T + ba + nproj[n]
//   out[n] += att[e] * exp(leaky(nap));  final: elu(out + bias)
// One warp per node; 2 passes of 8 edges; 32 f32x2 accumulators per warp.
// ---------------------------------------------------------------------------
__global__ __launch_bounds__(256, 1) void k_main(
    const float* __restrict__ neighbors, const float* __restrict__ aspects,
    const float* __restrict__ att, const float* __restrict__ ba,
    const float* __restrict__ bias, float* __restrict__ out) {

    extern __shared__ float sm[];
    float* sU = sm;                         // [2*128][PITCH]
    float* sRowBase = sm + 2 * FD * PITCH;  // [8 warps][8 rows][2 mats][128]

    // cooperative copy of U (2*128*132 floats) into SMEM
    {
        const float4* src = reinterpret_cast<const float4*>(g_U);
        float4* dst = reinterpret_cast<float4*>(sU);
        for (int i = threadIdx.x; i < (2 * FD * PITCH) / 4; i += 256) dst[i] = src[i];
    }
    __syncthreads();

    const int warp = threadIdx.x >> 5, lane = threadIdx.x & 31;
    float* sR = sRowBase + warp * (8 * 2 * FD);

    const ulonglong2* up[2][4];
#pragma unroll
    for (int m = 0; m < 2; ++m)
#pragma unroll
        for (int j = 0; j < 4; ++j)
            up[m][j] = reinterpret_cast<const ulonglong2*>(sU + (m * FD + lane + 32 * j) * PITCH);

    float ba4[4], bias4[4];
#pragma unroll
    for (int j = 0; j < 4; ++j) {
        ba4[j]   = __ldg(ba + lane + 32 * j);
        bias4[j] = __ldg(bias + lane + 32 * j);
    }

    const int gwarp = blockIdx.x * 8 + warp;
    const int nwarps = gridDim.x * 8;

    for (int node = gwarp; node < NN; node += nwarps) {
        float c[4], accout[4];
#pragma unroll
        for (int j = 0; j < 4; ++j) {
            c[j] = ba4[j] + __ldg(&g_nproj[(size_t)node * FD + lane + 32 * j]);
            accout[j] = 0.f;
        }

#pragma unroll 1
        for (int pass = 0; pass < 2; ++pass) {
            const int ebase = node * KNB + pass * 8;
#pragma unroll
            for (int r = 0; r < 8; ++r) {
                float4 vn = reinterpret_cast<const float4*>(neighbors + (size_t)(ebase + r) * FD)[lane];
                float4 va = reinterpret_cast<const float4*>(aspects   + (size_t)(ebase + r) * FD)[lane];
                reinterpret_cast<float4*>(sR + (r * 2 + 0) * FD)[lane] = vn;
                reinterpret_cast<float4*>(sR + (r * 2 + 1) * FD)[lane] = va;
            }
            __syncwarp();

            unsigned long long acc[8][4];
#pragma unroll
            for (int r = 0; r < 8; ++r)
#pragma unroll
                for (int j = 0; j < 4; ++j) acc[r][j] = 0ull;

#pragma unroll 4
            for (int k4 = 0; k4 < 32; ++k4) {
                ulonglong2 u[2][4];
#pragma unroll
                for (int m = 0; m < 2; ++m)
#pragma unroll
                    for (int j = 0; j < 4; ++j) u[m][j] = up[m][j][k4];
#pragma unroll
                for (int r = 0; r < 8; ++r) {
                    ulonglong2 an = reinterpret_cast<const ulonglong2*>(sR + (r * 2 + 0) * FD)[k4];
                    ulonglong2 aa = reinterpret_cast<const ulonglong2*>(sR + (r * 2 + 1) * FD)[k4];
#pragma unroll
                    for (int j = 0; j < 4; ++j) {
                        fma2(acc[r][j], an.x, u[0][j].x);
                        fma2(acc[r][j], an.y, u[0][j].y);
                        fma2(acc[r][j], aa.x, u[1][j].x);
                        fma2(acc[r][j], aa.y, u[1][j].y);
                    }
                }
            }

#pragma unroll
            for (int r = 0; r < 8; ++r) {
                float w = __ldg(att + ebase + r);
#pragma unroll
                for (int j = 0; j < 4; ++j) {
                    float v = hsum2(acc[r][j]) + c[j];
                    float l = fmaxf(v, 0.f) + NEG * fminf(v, 0.f);
                    accout[j] += w * __expf(l);
                }
            }
            __syncwarp();
        }

#pragma unroll
        for (int j = 0; j < 4; ++j) {
            float x = accout[j] + bias4[j];
            out[(size_t)node * FD + lane + 32 * j] = (x > 0.f) ? x : expm1f(x);
        }
    }
}

// ---------------------------------------------------------------------------
extern "C" void kernel_launch(void* const* d_in, const int* in_sizes, int n_in,
                              void* d_out, int out_size) {
    const float* nodes     = (const float*)d_in[0];
    const float* neighbors = (const float*)d_in[1];
    const float* aspects   = (const float*)d_in[2];
    const float* att       = (const float*)d_in[3];
    const float* W         = (const float*)d_in[4];
    const float* Wa        = (const float*)d_in[5];
    const float* ba        = (const float*)d_in[6];
    const float* bias      = (const float*)d_in[7];
    float* out = (float*)d_out;

    const int smem_nproj = (FD * PITCH + 8 * 8 * FD) * sizeof(float);            // 100352
    const int smem_main  = (2 * FD * PITCH + 8 * 8 * 2 * FD) * sizeof(float);    // 200704
    cudaFuncSetAttribute(k_nproj, cudaFuncAttributeMaxDynamicSharedMemorySize, smem_nproj);
    cudaFuncSetAttribute(k_main,  cudaFuncAttributeMaxDynamicSharedMemorySize, smem_main);

    k_computeU<<<256, 128>>>(W, Wa);
    k_nproj<<<512, 256, smem_nproj>>>(nodes, W);
    k_main<<<1024, 256, smem_main>>>(neighbors, aspects, att, ba, bias, out);
}

// round 3
// speedup vs baseline: 1.3302x; 1.3302x over previous
#include <cuda_runtime.h>
#include <cuda_bf16.h>
#include <cstdint>

#define NN     32768
#define KNB    16
#define FD     128
#define NEG    0.2f
#define NTILES 4096          // 524288 edges / 128

// ---------------- device scratch ----------------
__device__ __align__(16) float g_U[2 * FD * FD];     // U[m][o][f] fp32
__device__ __align__(16) float g_nproj[NN * FD];     // nodes @ W^T

// ---------------- smem layout for k_main ----------------
#define PB_BYTES  528        // B row pitch: 264 bf16 (256 K + 8 pad)
#define PA_BYTES  144        // A row pitch: 72 bf16 (64 K + 8 pad)
#define SM_BHI    0
#define SM_BLO    67584      // 128 * 528
#define SM_A      135168
#define A_SPLIT   18432      // 128 * 144
#define A_STAGE   36864      // hi + lo
#define SMEM_MAIN 208896     // 135168 + 2*36864

// ---------------- helpers ----------------
__device__ __forceinline__ uint32_t smem_u32(const void* p) {
    uint32_t a;
    asm("{ .reg .u64 t; cvta.to.shared.u64 t, %1; cvt.u32.u64 %0, t; }" : "=r"(a) : "l"(p));
    return a;
}

__device__ __forceinline__ void split4(float4 x, uint2& h, uint2& l) {
    __nv_bfloat162 hA = __floats2bfloat162_rn(x.x, x.y);
    __nv_bfloat162 hB = __floats2bfloat162_rn(x.z, x.w);
    float r0 = x.x - __low2float(hA), r1 = x.y - __high2float(hA);
    float r2 = x.z - __low2float(hB), r3 = x.w - __high2float(hB);
    __nv_bfloat162 lA = __floats2bfloat162_rn(r0, r1);
    __nv_bfloat162 lB = __floats2bfloat162_rn(r2, r3);
    h.x = *reinterpret_cast<uint32_t*>(&hA); h.y = *reinterpret_cast<uint32_t*>(&hB);
    l.x = *reinterpret_cast<uint32_t*>(&lA); l.y = *reinterpret_cast<uint32_t*>(&lB);
}

#define LDSM4(r, addr) \
    asm volatile("ldmatrix.sync.aligned.m8n8.x4.shared.b16 {%0,%1,%2,%3}, [%4];" \
        : "=r"((r)[0]), "=r"((r)[1]), "=r"((r)[2]), "=r"((r)[3]) : "r"(addr))

#define MMA(d, a, b0_, b1_) \
    asm volatile("mma.sync.aligned.m16n8k16.row.col.f32.bf16.bf16.f32 " \
        "{%0,%1,%2,%3}, {%4,%5,%6,%7}, {%8,%9}, {%0,%1,%2,%3};" \
        : "+f"((d)[0]), "+f"((d)[1]), "+f"((d)[2]), "+f"((d)[3]) \
        : "r"((a)[0]), "r"((a)[1]), "r"((a)[2]), "r"((a)[3]), "r"(b0_), "r"(b1_))

// ---------------------------------------------------------------------------
// U[m][o][f] = sum_op Wa[o][m*128+op] * W[op][f]
// ---------------------------------------------------------------------------
__global__ __launch_bounds__(256) void k_computeU(const float* __restrict__ W,
                                                  const float* __restrict__ Wa) {
    extern __shared__ float sW[];   // [128][128]
    for (int i = threadIdx.x; i < FD * FD; i += 256) sW[i] = W[i];
    __syncthreads();
    const int f = threadIdx.x & 127, h = threadIdx.x >> 7;
    const int R0 = blockIdx.x * 16 + h * 8;
#pragma unroll 1
    for (int rr = 0; rr < 8; ++rr) {
        const int R = R0 + rr, m = R >> 7, o = R & 127;
        const float* wa = Wa + o * 256 + m * 128;
        float acc = 0.f;
#pragma unroll 8
        for (int op = 0; op < FD; ++op) acc += __ldg(wa + op) * sW[op * FD + f];
        g_U[R * FD + f] = acc;
    }
}

// ---------------------------------------------------------------------------
// nproj[n][o] = sum_f nodes[n][f] * W[o][f]   (fp32x2 FMA, proven in R1)
// ---------------------------------------------------------------------------
#define PITCH 132
__device__ __forceinline__ void fma2(unsigned long long &d, unsigned long long a, unsigned long long b) {
    asm("fma.rn.f32x2 %0, %1, %2, %0;" : "+l"(d) : "l"(a), "l"(b));
}
__device__ __forceinline__ float hsum2(unsigned long long v) {
    float lo, hi;
    asm("mov.b64 {%0, %1}, %2;" : "=f"(lo), "=f"(hi) : "l"(v));
    return lo + hi;
}
__global__ __launch_bounds__(256, 2) void k_nproj(const float* __restrict__ nodes,
                                                  const float* __restrict__ W) {
    extern __shared__ float smf[];
    float* sW = smf;
    float* sRowBase = smf + FD * PITCH;
    for (int i = threadIdx.x; i < FD * FD; i += 256)
        sW[(i >> 7) * PITCH + (i & 127)] = W[i];
    __syncthreads();
    const int warp = threadIdx.x >> 5, lane = threadIdx.x & 31;
    float* sR = sRowBase + warp * 8 * FD;
    const int base = (blockIdx.x * 8 + warp) * 8;
    if (base >= NN) return;
#pragma unroll
    for (int r = 0; r < 8; ++r) {
        float4 v = reinterpret_cast<const float4*>(nodes + (size_t)(base + r) * FD)[lane];
        reinterpret_cast<float4*>(sR + r * FD)[lane] = v;
    }
    __syncwarp();
    const ulonglong2* up[4];
#pragma unroll
    for (int j = 0; j < 4; ++j)
        up[j] = reinterpret_cast<const ulonglong2*>(sW + (lane + 32 * j) * PITCH);
    unsigned long long acc[8][4];
#pragma unroll
    for (int r = 0; r < 8; ++r)
#pragma unroll
        for (int j = 0; j < 4; ++j) acc[r][j] = 0ull;
#pragma unroll 4
    for (int k4 = 0; k4 < 32; ++k4) {
        ulonglong2 u[4];
#pragma unroll
        for (int j = 0; j < 4; ++j) u[j] = up[j][k4];
#pragma unroll
        for (int r = 0; r < 8; ++r) {
            ulonglong2 a = reinterpret_cast<const ulonglong2*>(sR + r * FD)[k4];
#pragma unroll
            for (int j = 0; j < 4; ++j) { fma2(acc[r][j], a.x, u[j].x); fma2(acc[r][j], a.y, u[j].y); }
        }
    }
#pragma unroll
    for (int r = 0; r < 8; ++r)
#pragma unroll
        for (int j = 0; j < 4; ++j)
            g_nproj[(size_t)(base + r) * FD + lane + 32 * j] = hsum2(acc[r][j]);
}

// ---------------------------------------------------------------------------
// Main: persistent HMMA kernel. Tile = 128 edges x 128 out, K=256 (neigh|asp),
// 3-term bf16 split (hh + hl + lh). 8 warps: 2(M) x 4(N), warp tile 64x32.
// ---------------------------------------------------------------------------
__global__ __launch_bounds__(256, 1) void k_main(
    const float* __restrict__ neighbors, const float* __restrict__ aspects,
    const float* __restrict__ att, const float* __restrict__ ba,
    const float* __restrict__ bias, float* __restrict__ out) {

    extern __shared__ __align__(16) char sm[];
    const int tid = threadIdx.x, lane = tid & 31, wid = tid >> 5;
    const int warp_m = wid >> 2, warp_n = wid & 3;
    const int m0 = warp_m * 64, n0 = warp_n * 32;
    const uint32_t smBase = smem_u32(sm);

    // ---- build resident B (U1|U2 as bf16 hi/lo), K-major rows per n ----
    for (int idx = tid; idx < 8192; idx += 256) {
        float4 x = __ldg(reinterpret_cast<const float4*>(g_U) + idx);
        uint2 h, l; split4(x, h, l);
        const int f4 = idx & 31, o = (idx >> 5) & 127, m = idx >> 12;
        const int off = o * PB_BYTES + (m * 128 + f4 * 4) * 2;
        *reinterpret_cast<uint2*>(sm + SM_BHI + off) = h;
        *reinterpret_cast<uint2*>(sm + SM_BLO + off) = l;
    }

    // ---- per-thread epilogue constants ----
    const int q = lane & 3, r = lane >> 2;
    float baR[8], biasR[8];
#pragma unroll
    for (int nt = 0; nt < 4; ++nt)
#pragma unroll
        for (int i = 0; i < 2; ++i) {
            const int col = n0 + nt * 8 + q * 2 + i;
            baR[nt * 2 + i]   = __ldg(ba + col);
            biasR[nt * 2 + i] = __ldg(bias + col);
        }
    __syncthreads();

    float acc[4][4][4];
#pragma unroll
    for (int mt = 0; mt < 4; ++mt)
#pragma unroll
        for (int nt = 0; nt < 4; ++nt)
#pragma unroll
            for (int i = 0; i < 4; ++i) acc[mt][nt][i] = 0.f;

    // ldmatrix lane base offsets
    const int lane15 = lane & 15, laneHi = lane >> 4;
    const uint32_t aRowOff = (uint32_t)((m0 + lane15) * PA_BYTES + laneHi * 16);
    const uint32_t bRowHi  = smBase + SM_BHI + (n0 + lane15) * PB_BYTES + laneHi * 16;
    const uint32_t bRowLo  = bRowHi + (SM_BLO - SM_BHI);

    const int grid = gridDim.x;
    float4 raw[8];
    int tile = blockIdx.x;
    if (tile < NTILES) {   // prologue: chunk 0
        const float* src = neighbors + (size_t)tile * 16384 + (tid >> 4) * 128 + (tid & 15) * 4;
#pragma unroll
        for (int j = 0; j < 8; ++j)
            raw[j] = __ldg(reinterpret_cast<const float4*>(src + j * 2048));
    }

#pragma unroll 1
    for (; tile < NTILES; tile += grid) {
#pragma unroll 1
        for (int c = 0; c < 4; ++c) {
            const int stage = c & 1;
            // STS current chunk (fp32 -> bf16 hi/lo split)
            {
                char* hiP = sm + SM_A + stage * A_STAGE;
                char* loP = hiP + A_SPLIT;
                const int mb = tid >> 4, sub = tid & 15;
#pragma unroll
                for (int j = 0; j < 8; ++j) {
                    uint2 h, l; split4(raw[j], h, l);
                    const int row = mb + j * 16;
                    *reinterpret_cast<uint2*>(hiP + row * PA_BYTES + sub * 8) = h;
                    *reinterpret_cast<uint2*>(loP + row * PA_BYTES + sub * 8) = l;
                }
            }
            __syncthreads();
            // prefetch next chunk (or next tile's chunk 0)
            {
                int nc = c + 1, nt_ = tile;
                if (nc == 4) { nc = 0; nt_ = tile + grid; }
                if (nt_ < NTILES) {
                    const float* base = (nc < 2) ? neighbors : aspects;
                    const float* src = base + (size_t)nt_ * 16384 + (nc & 1) * 64
                                     + (tid >> 4) * 128 + (tid & 15) * 4;
#pragma unroll
                    for (int j = 0; j < 8; ++j)
                        raw[j] = __ldg(reinterpret_cast<const float4*>(src + j * 2048));
                }
            }
            // MMA on chunk c
            {
                const uint32_t aHi = smBase + SM_A + stage * A_STAGE + aRowOff;
                const uint32_t aLo = aHi + A_SPLIT;
                const uint32_t bC  = (uint32_t)(c * 128);   // k byte offset in B rows
#pragma unroll
                for (int ks = 0; ks < 4; ++ks) {
                    const uint32_t ko = ks * 32;
                    uint32_t ah[4][4], al[4][4], bh[2][4], bl[2][4];
#pragma unroll
                    for (int mt = 0; mt < 4; ++mt) LDSM4(ah[mt], aHi + mt * (16 * PA_BYTES) + ko);
#pragma unroll
                    for (int mt = 0; mt < 4; ++mt) LDSM4(al[mt], aLo + mt * (16 * PA_BYTES) + ko);
                    LDSM4(bh[0], bRowHi + bC + ko);
                    LDSM4(bh[1], bRowHi + 16 * PB_BYTES + bC + ko);
                    LDSM4(bl[0], bRowLo + bC + ko);
                    LDSM4(bl[1], bRowLo + 16 * PB_BYTES + bC + ko);
#pragma unroll
                    for (int mt = 0; mt < 4; ++mt)
#pragma unroll
                        for (int nt = 0; nt < 4; ++nt) {
                            const int g = nt >> 1, s = nt & 1;
                            MMA(acc[mt][nt], ah[mt], bh[g][s], bh[g][2 + s]);
                            MMA(acc[mt][nt], ah[mt], bl[g][s], bl[g][2 + s]);
                            MMA(acc[mt][nt], al[mt], bh[g][s], bh[g][2 + s]);
                        }
                }
            }
            __syncthreads();
        }

        // ---- epilogue: leaky->exp->att-weight, reduce 16 edges/node, elu, store ----
#pragma unroll
        for (int mt = 0; mt < 4; ++mt) {
            const int edge0 = tile * 128 + m0 + mt * 16;
            const float attA = __ldg(att + edge0 + r);
            const float attB = __ldg(att + edge0 + 8 + r);
            const int node = edge0 >> 4;
            const float* np = g_nproj + (size_t)node * FD;
#pragma unroll
            for (int nt = 0; nt < 4; ++nt) {
                const int col0 = n0 + nt * 8 + q * 2;
                const float nb0 = __ldg(np + col0)     + baR[nt * 2];
                const float nb1 = __ldg(np + col0 + 1) + baR[nt * 2 + 1];
                float* a4 = acc[mt][nt];
                float v0 = a4[0] + nb0, v1 = a4[1] + nb1;
                float v2 = a4[2] + nb0, v3 = a4[3] + nb1;
                v0 = fmaxf(v0, 0.f) + NEG * fminf(v0, 0.f);
                v1 = fmaxf(v1, 0.f) + NEG * fminf(v1, 0.f);
                v2 = fmaxf(v2, 0.f) + NEG * fminf(v2, 0.f);
                v3 = fmaxf(v3, 0.f) + NEG * fminf(v3, 0.f);
                float s0 = attA * __expf(v0) + attB * __expf(v2);
                float s1 = attA * __expf(v1) + attB * __expf(v3);
                s0 += __shfl_xor_sync(0xFFFFFFFFu, s0, 4);
                s1 += __shfl_xor_sync(0xFFFFFFFFu, s1, 4);
                s0 += __shfl_xor_sync(0xFFFFFFFFu, s0, 8);
                s1 += __shfl_xor_sync(0xFFFFFFFFu, s1, 8);
                s0 += __shfl_xor_sync(0xFFFFFFFFu, s0, 16);
                s1 += __shfl_xor_sync(0xFFFFFFFFu, s1, 16);
                if (r == 0) {
                    float x0 = s0 + biasR[nt * 2];
                    float x1 = s1 + biasR[nt * 2 + 1];
                    float2 o2;
                    o2.x = (x0 > 0.f) ? x0 : expm1f(x0);
                    o2.y = (x1 > 0.f) ? x1 : expm1f(x1);
                    *reinterpret_cast<float2*>(out + (size_t)node * FD + col0) = o2;
                }
                a4[0] = a4[1] = a4[2] = a4[3] = 0.f;
            }
        }
    }
}

// ---------------------------------------------------------------------------
extern "C" void kernel_launch(void* const* d_in, const int* in_sizes, int n_in,
                              void* d_out, int out_size) {
    const float* nodes     = (const float*)d_in[0];
    const float* neighbors = (const float*)d_in[1];
    const float* aspects   = (const float*)d_in[2];
    const float* att       = (const float*)d_in[3];
    const float* W         = (const float*)d_in[4];
    const float* Wa        = (const float*)d_in[5];
    const float* ba        = (const float*)d_in[6];
    const float* bias      = (const float*)d_in[7];
    float* out = (float*)d_out;

    int dev = 0, nsm = 148;
    cudaGetDevice(&dev);
    cudaDeviceGetAttribute(&nsm, cudaDevAttrMultiProcessorCount, dev);

    const int smem_u     = FD * FD * sizeof(float);                      // 65536
    const int smem_nproj = (FD * PITCH + 8 * 8 * FD) * sizeof(float);    // 100352
    cudaFuncSetAttribute(k_computeU, cudaFuncAttributeMaxDynamicSharedMemorySize, smem_u);
    cudaFuncSetAttribute(k_nproj,    cudaFuncAttributeMaxDynamicSharedMemorySize, smem_nproj);
    cudaFuncSetAttribute(k_main,     cudaFuncAttributeMaxDynamicSharedMemorySize, SMEM_MAIN);

    k_computeU<<<16, 256, smem_u>>>(W, Wa);
    k_nproj<<<512, 256, smem_nproj>>>(nodes, W);
    k_main<<<nsm, 256, SMEM_MAIN>>>(neighbors, aspects, att, ba, bias, out);
}

// round 4
// speedup vs baseline: 1.8034x; 1.3557x over previous
#include <cuda_runtime.h>
#include <cuda_bf16.h>
#include <cstdint>

#define NN     32768
#define KNB    16
#define FD     128
#define NEG    0.2f
#define NTILES 4096          // 524288 edges / 128

// ---------------- device scratch ----------------
__device__ __align__(16) float g_U[2 * FD * FD];     // U[m][o][f] fp32
__device__ __align__(16) float g_nproj[NN * FD];     // nodes @ W^T

// ---------------- smem layout for k_main ----------------
#define PB_BYTES  528        // B row pitch bytes: 264 bf16 (256 K + 8 pad)
#define PA_BYTES  144        // A row pitch bytes: 72 bf16 (64 K + 8 pad)
#define SM_BHI    0
#define SM_BLO    67584      // 128 * 528
#define SM_A      135168
#define A_SPLIT   18432      // 128 * 144
#define A_STAGE   36864      // hi + lo
#define SMEM_MAIN 208896     // 135168 + 2*36864

// ---------------- helpers ----------------
__device__ __forceinline__ uint32_t smem_u32(const void* p) {
    uint32_t a;
    asm("{ .reg .u64 t; cvta.to.shared.u64 t, %1; cvt.u32.u64 %0, t; }" : "=r"(a) : "l"(p));
    return a;
}

__device__ __forceinline__ void split4(float4 x, uint2& h, uint2& l) {
    __nv_bfloat162 hA = __floats2bfloat162_rn(x.x, x.y);
    __nv_bfloat162 hB = __floats2bfloat162_rn(x.z, x.w);
    float r0 = x.x - __low2float(hA), r1 = x.y - __high2float(hA);
    float r2 = x.z - __low2float(hB), r3 = x.w - __high2float(hB);
    __nv_bfloat162 lA = __floats2bfloat162_rn(r0, r1);
    __nv_bfloat162 lB = __floats2bfloat162_rn(r2, r3);
    h.x = *reinterpret_cast<uint32_t*>(&hA); h.y = *reinterpret_cast<uint32_t*>(&hB);
    l.x = *reinterpret_cast<uint32_t*>(&lA); l.y = *reinterpret_cast<uint32_t*>(&lB);
}

#define LDSM4(r, addr) \
    asm volatile("ldmatrix.sync.aligned.m8n8.x4.shared.b16 {%0,%1,%2,%3}, [%4];" \
        : "=r"((r)[0]), "=r"((r)[1]), "=r"((r)[2]), "=r"((r)[3]) : "r"(addr))

#define MMA(d, a, b0_, b1_) \
    asm volatile("mma.sync.aligned.m16n8k16.row.col.f32.bf16.bf16.f32 " \
        "{%0,%1,%2,%3}, {%4,%5,%6,%7}, {%8,%9}, {%0,%1,%2,%3};" \
        : "+f"((d)[0]), "+f"((d)[1]), "+f"((d)[2]), "+f"((d)[3]) \
        : "r"((a)[0]), "r"((a)[1]), "r"((a)[2]), "r"((a)[3]), "r"(b0_), "r"(b1_))

// ---------------------------------------------------------------------------
// U[m][o][f] = sum_op Wa[o][m*128+op] * W[op][f]
// grid 256 (one output row each), 128 threads; W staged in smem.
// ---------------------------------------------------------------------------
__global__ __launch_bounds__(128) void k_computeU(const float* __restrict__ W,
                                                  const float* __restrict__ Wa) {
    extern __shared__ float sW[];   // [128][128]
    {
        const float4* src = reinterpret_cast<const float4*>(W);
        float4* dst = reinterpret_cast<float4*>(sW);
#pragma unroll
        for (int i = 0; i < 32; ++i) dst[threadIdx.x + i * 128] = __ldg(src + threadIdx.x + i * 128);
    }
    __syncthreads();
    const int f = threadIdx.x;
    const int R = blockIdx.x, m = R >> 7, o = R & 127;
    const float* wa = Wa + o * 256 + m * 128;
    float acc = 0.f;
#pragma unroll 16
    for (int op = 0; op < FD; ++op) acc += __ldg(wa + op) * sW[op * FD + f];
    g_U[R * FD + f] = acc;
}

// ---------------------------------------------------------------------------
// nproj[n][o] = sum_f nodes[n][f] * W[o][f]   (fp32x2 FMA, proven in R1)
// ---------------------------------------------------------------------------
#define PITCH 132
__device__ __forceinline__ void fma2(unsigned long long &d, unsigned long long a, unsigned long long b) {
    asm("fma.rn.f32x2 %0, %1, %2, %0;" : "+l"(d) : "l"(a), "l"(b));
}
__device__ __forceinline__ float hsum2(unsigned long long v) {
    float lo, hi;
    asm("mov.b64 {%0, %1}, %2;" : "=f"(lo), "=f"(hi) : "l"(v));
    return lo + hi;
}
__global__ __launch_bounds__(256, 2) void k_nproj(const float* __restrict__ nodes,
                                                  const float* __restrict__ W) {
    extern __shared__ float smf[];
    float* sW = smf;
    float* sRowBase = smf + FD * PITCH;
    for (int i = threadIdx.x; i < FD * FD; i += 256)
        sW[(i >> 7) * PITCH + (i & 127)] = W[i];
    __syncthreads();
    const int warp = threadIdx.x >> 5, lane = threadIdx.x & 31;
    float* sR = sRowBase + warp * 8 * FD;
    const int base = (blockIdx.x * 8 + warp) * 8;
    if (base >= NN) return;
#pragma unroll
    for (int r = 0; r < 8; ++r) {
        float4 v = reinterpret_cast<const float4*>(nodes + (size_t)(base + r) * FD)[lane];
        reinterpret_cast<float4*>(sR + r * FD)[lane] = v;
    }
    __syncwarp();
    const ulonglong2* up[4];
#pragma unroll
    for (int j = 0; j < 4; ++j)
        up[j] = reinterpret_cast<const ulonglong2*>(sW + (lane + 32 * j) * PITCH);
    unsigned long long acc[8][4];
#pragma unroll
    for (int r = 0; r < 8; ++r)
#pragma unroll
        for (int j = 0; j < 4; ++j) acc[r][j] = 0ull;
#pragma unroll 4
    for (int k4 = 0; k4 < 32; ++k4) {
        ulonglong2 u[4];
#pragma unroll
        for (int j = 0; j < 4; ++j) u[j] = up[j][k4];
#pragma unroll
        for (int r = 0; r < 8; ++r) {
            ulonglong2 a = reinterpret_cast<const ulonglong2*>(sR + r * FD)[k4];
#pragma unroll
            for (int j = 0; j < 4; ++j) { fma2(acc[r][j], a.x, u[j].x); fma2(acc[r][j], a.y, u[j].y); }
        }
    }
#pragma unroll
    for (int r = 0; r < 8; ++r)
#pragma unroll
        for (int j = 0; j < 4; ++j)
            g_nproj[(size_t)(base + r) * FD + lane + 32 * j] = hsum2(acc[r][j]);
}

// ---------------------------------------------------------------------------
// Main: persistent HMMA kernel. Tile = 128 edges x 128 out, K=256 (neigh|asp),
// 3-term bf16 split (hh + hl + lh), TERM-MAJOR to break accumulator RAW.
// 16 warps: 4(M) x 4(N), warp tile 32x32.
// ---------------------------------------------------------------------------
__global__ __launch_bounds__(512, 1) void k_main(
    const float* __restrict__ neighbors, const float* __restrict__ aspects,
    const float* __restrict__ att, const float* __restrict__ ba,
    const float* __restrict__ bias, float* __restrict__ out) {

    extern __shared__ __align__(16) char sm[];
    const int tid = threadIdx.x, lane = tid & 31, wid = tid >> 5;
    const int warp_m = wid >> 2, warp_n = wid & 3;
    const int m0 = warp_m * 32, n0 = warp_n * 32;
    const uint32_t smBase = smem_u32(sm);

    // ---- build resident B (U1|U2 as bf16 hi/lo), K-major rows per output col ----
    for (int idx = tid; idx < 8192; idx += 512) {
        float4 x = __ldg(reinterpret_cast<const float4*>(g_U) + idx);
        uint2 h, l; split4(x, h, l);
        const int f4 = idx & 31, o = (idx >> 5) & 127, m = idx >> 12;
        const int off = o * PB_BYTES + (m * 128 + f4 * 4) * 2;
        *reinterpret_cast<uint2*>(sm + SM_BHI + off) = h;
        *reinterpret_cast<uint2*>(sm + SM_BLO + off) = l;
    }

    // ---- per-thread epilogue constants ----
    const int q = lane & 3, r = lane >> 2;
    float baR[8], biasR[8];
#pragma unroll
    for (int nt = 0; nt < 4; ++nt)
#pragma unroll
        for (int i = 0; i < 2; ++i) {
            const int col = n0 + nt * 8 + q * 2 + i;
            baR[nt * 2 + i]   = __ldg(ba + col);
            biasR[nt * 2 + i] = __ldg(bias + col);
        }
    __syncthreads();

    float acc[2][4][4];
#pragma unroll
    for (int mt = 0; mt < 2; ++mt)
#pragma unroll
        for (int nt = 0; nt < 4; ++nt)
#pragma unroll
            for (int i = 0; i < 4; ++i) acc[mt][nt][i] = 0.f;

    // ldmatrix lane base offsets
    const int lane15 = lane & 15, laneHi = lane >> 4;
    const uint32_t aRowOff = (uint32_t)((m0 + lane15) * PA_BYTES + laneHi * 16);
    const uint32_t bRowHi  = smBase + SM_BHI + (n0 + lane15) * PB_BYTES + laneHi * 16;
    const uint32_t bRowLo  = bRowHi + (SM_BLO - SM_BHI);

    const int grid = gridDim.x;
    float4 raw[4];
    int tile = blockIdx.x;
    if (tile < NTILES) {   // prologue: chunk 0 of first tile
        const float* src = neighbors + (size_t)tile * 16384 + (tid >> 4) * 128 + (tid & 15) * 4;
#pragma unroll
        for (int j = 0; j < 4; ++j)
            raw[j] = __ldg(reinterpret_cast<const float4*>(src + j * 4096));
    }

#pragma unroll 1
    for (; tile < NTILES; tile += grid) {
#pragma unroll 1
        for (int c = 0; c < 4; ++c) {
            const int stage = c & 1;
            // STS current chunk (fp32 -> bf16 hi/lo split)
            {
                char* hiP = sm + SM_A + stage * A_STAGE;
                char* loP = hiP + A_SPLIT;
                const int mb = tid >> 4, sub = tid & 15;
#pragma unroll
                for (int j = 0; j < 4; ++j) {
                    uint2 h, l; split4(raw[j], h, l);
                    const int row = mb + j * 32;
                    *reinterpret_cast<uint2*>(hiP + row * PA_BYTES + sub * 8) = h;
                    *reinterpret_cast<uint2*>(loP + row * PA_BYTES + sub * 8) = l;
                }
            }
            __syncthreads();
            // prefetch next chunk (or next tile's chunk 0)
            {
                int nc = c + 1, nt_ = tile;
                if (nc == 4) { nc = 0; nt_ = tile + grid; }
                if (nt_ < NTILES) {
                    const float* base = (nc < 2) ? neighbors : aspects;
                    const float* src = base + (size_t)nt_ * 16384 + (nc & 1) * 64
                                     + (tid >> 4) * 128 + (tid & 15) * 4;
#pragma unroll
                    for (int j = 0; j < 4; ++j)
                        raw[j] = __ldg(reinterpret_cast<const float4*>(src + j * 4096));
                }
            }
            // MMA on chunk c — term-major to keep 8 independent MMAs in flight
            {
                const uint32_t aHi = smBase + SM_A + stage * A_STAGE + aRowOff;
                const uint32_t aLo = aHi + A_SPLIT;
                const uint32_t bC  = (uint32_t)(c * 128);   // k byte offset in B rows
#pragma unroll
                for (int ks = 0; ks < 4; ++ks) {
                    const uint32_t ko = ks * 32;
                    uint32_t ah[2][4], al[2][4], bh[2][4], bl[2][4];
#pragma unroll
                    for (int mt = 0; mt < 2; ++mt) LDSM4(ah[mt], aHi + mt * (16 * PA_BYTES) + ko);
#pragma unroll
                    for (int mt = 0; mt < 2; ++mt) LDSM4(al[mt], aLo + mt * (16 * PA_BYTES) + ko);
                    LDSM4(bh[0], bRowHi + bC + ko);
                    LDSM4(bh[1], bRowHi + 16 * PB_BYTES + bC + ko);
                    LDSM4(bl[0], bRowLo + bC + ko);
                    LDSM4(bl[1], bRowLo + 16 * PB_BYTES + bC + ko);
                    // term hh
#pragma unroll
                    for (int mt = 0; mt < 2; ++mt)
#pragma unroll
                        for (int nt = 0; nt < 4; ++nt) {
                            const int g = nt >> 1, s = nt & 1;
                            MMA(acc[mt][nt], ah[mt], bh[g][s], bh[g][2 + s]);
                        }
                    // term hl
#pragma unroll
                    for (int mt = 0; mt < 2; ++mt)
#pragma unroll
                        for (int nt = 0; nt < 4; ++nt) {
                            const int g = nt >> 1, s = nt & 1;
                            MMA(acc[mt][nt], ah[mt], bl[g][s], bl[g][2 + s]);
                        }
                    // term lh
#pragma unroll
                    for (int mt = 0; mt < 2; ++mt)
#pragma unroll
                        for (int nt = 0; nt < 4; ++nt) {
                            const int g = nt >> 1, s = nt & 1;
                            MMA(acc[mt][nt], al[mt], bh[g][s], bh[g][2 + s]);
                        }
                }
            }
            __syncthreads();
        }

        // ---- epilogue: leaky->exp->att-weight, reduce 16 edges/node, elu, store ----
#pragma unroll
        for (int mt = 0; mt < 2; ++mt) {
            const int edge0 = tile * 128 + m0 + mt * 16;
            const float attA = __ldg(att + edge0 + r);
            const float attB = __ldg(att + edge0 + 8 + r);
            const int node = edge0 >> 4;
            const float* np = g_nproj + (size_t)node * FD;
#pragma unroll
            for (int nt = 0; nt < 4; ++nt) {
                const int col0 = n0 + nt * 8 + q * 2;
                const float nb0 = __ldg(np + col0)     + baR[nt * 2];
                const float nb1 = __ldg(np + col0 + 1) + baR[nt * 2 + 1];
                float* a4 = acc[mt][nt];
                float v0 = a4[0] + nb0, v1 = a4[1] + nb1;
                float v2 = a4[2] + nb0, v3 = a4[3] + nb1;
                v0 = fmaxf(v0, 0.f) + NEG * fminf(v0, 0.f);
                v1 = fmaxf(v1, 0.f) + NEG * fminf(v1, 0.f);
                v2 = fmaxf(v2, 0.f) + NEG * fminf(v2, 0.f);
                v3 = fmaxf(v3, 0.f) + NEG * fminf(v3, 0.f);
                float s0 = attA * __expf(v0) + attB * __expf(v2);
                float s1 = attA * __expf(v1) + attB * __expf(v3);
                s0 += __shfl_xor_sync(0xFFFFFFFFu, s0, 4);
                s1 += __shfl_xor_sync(0xFFFFFFFFu, s1, 4);
                s0 += __shfl_xor_sync(0xFFFFFFFFu, s0, 8);
                s1 += __shfl_xor_sync(0xFFFFFFFFu, s1, 8);
                s0 += __shfl_xor_sync(0xFFFFFFFFu, s0, 16);
                s1 += __shfl_xor_sync(0xFFFFFFFFu, s1, 16);
                if (r == 0) {
                    float x0 = s0 + biasR[nt * 2];
                    float x1 = s1 + biasR[nt * 2 + 1];
                    float2 o2;
                    o2.x = (x0 > 0.f) ? x0 : expm1f(x0);
                    o2.y = (x1 > 0.f) ? x1 : expm1f(x1);
                    *reinterpret_cast<float2*>(out + (size_t)node * FD + col0) = o2;
                }
                a4[0] = a4[1] = a4[2] = a4[3] = 0.f;
            }
        }
    }
}

// ---------------------------------------------------------------------------
extern "C" void kernel_launch(void* const* d_in, const int* in_sizes, int n_in,
                              void* d_out, int out_size) {
    const float* nodes     = (const float*)d_in[0];
    const float* neighbors = (const float*)d_in[1];
    const float* aspects   = (const float*)d_in[2];
    const float* att       = (const float*)d_in[3];
    const float* W         = (const float*)d_in[4];
    const float* Wa        = (const float*)d_in[5];
    const float* ba        = (const float*)d_in[6];
    const float* bias      = (const float*)d_in[7];
    float* out = (float*)d_out;

    int dev = 0, nsm = 148;
    cudaGetDevice(&dev);
    cudaDeviceGetAttribute(&nsm, cudaDevAttrMultiProcessorCount, dev);

    const int smem_u     = FD * FD * sizeof(float);                      // 65536
    const int smem_nproj = (FD * PITCH + 8 * 8 * FD) * sizeof(float);    // 100352
    cudaFuncSetAttribute(k_computeU, cudaFuncAttributeMaxDynamicSharedMemorySize, smem_u);
    cudaFuncSetAttribute(k_nproj,    cudaFuncAttributeMaxDynamicSharedMemorySize, smem_nproj);
    cudaFuncSetAttribute(k_main,     cudaFuncAttributeMaxDynamicSharedMemorySize, SMEM_MAIN);

    k_computeU<<<256, 128, smem_u>>>(W, Wa);
    k_nproj<<<512, 256, smem_nproj>>>(nodes, W);
    k_main<<<nsm, 512, SMEM_MAIN>>>(neighbors, aspects, att, ba, bias, out);
}

// round 5
// speedup vs baseline: 2.9761x; 1.6503x over previous
#include <cuda_runtime.h>
#include <cuda_fp16.h>
#include <cstdint>

#define NN     32768
#define KNB    16
#define FD     128
#define NEG    0.2f
#define NTILES 4096          // 524288 edges / 128

// ---------------- device scratch ----------------
__device__ __align__(16) float g_U[2 * FD * FD];     // U[m][o][f] fp32
__device__ __align__(16) float g_nproj[NN * FD];     // nodes @ W^T

// ---------------- smem layout for k_main ----------------
#define PB_BYTES  528        // B row pitch bytes: 264 fp16 (256 K + 8 pad)
#define PA_BYTES  144        // A row pitch bytes: 72 fp16 (64 K + 8 pad)
#define SM_B      0
#define SM_A      67584      // 128 * 528
#define A_STAGE   18432      // 128 * 144
#define SMEM_MAIN 104448     // 67584 + 2*18432

// ---------------- helpers ----------------
__device__ __forceinline__ uint32_t smem_u32(const void* p) {
    uint32_t a;
    asm("{ .reg .u64 t; cvta.to.shared.u64 t, %1; cvt.u32.u64 %0, t; }" : "=r"(a) : "l"(p));
    return a;
}

__device__ __forceinline__ uint2 cvt4(float4 x) {
    __half2 a = __floats2half2_rn(x.x, x.y);
    __half2 b = __floats2half2_rn(x.z, x.w);
    uint2 r;
    r.x = *reinterpret_cast<uint32_t*>(&a);
    r.y = *reinterpret_cast<uint32_t*>(&b);
    return r;
}

#define LDSM4(r, addr) \
    asm volatile("ldmatrix.sync.aligned.m8n8.x4.shared.b16 {%0,%1,%2,%3}, [%4];" \
        : "=r"((r)[0]), "=r"((r)[1]), "=r"((r)[2]), "=r"((r)[3]) : "r"(addr))

#define MMA(d, a, b0_, b1_) \
    asm volatile("mma.sync.aligned.m16n8k16.row.col.f32.f16.f16.f32 " \
        "{%0,%1,%2,%3}, {%4,%5,%6,%7}, {%8,%9}, {%0,%1,%2,%3};" \
        : "+f"((d)[0]), "+f"((d)[1]), "+f"((d)[2]), "+f"((d)[3]) \
        : "r"((a)[0]), "r"((a)[1]), "r"((a)[2]), "r"((a)[3]), "r"(b0_), "r"(b1_))

// ---------------------------------------------------------------------------
// U[m][o][f] = sum_op Wa[o][m*128+op] * W[op][f]
// ---------------------------------------------------------------------------
__global__ __launch_bounds__(128) void k_computeU(const float* __restrict__ W,
                                                  const float* __restrict__ Wa) {
    extern __shared__ float sW[];   // [128][128]
    {
        const float4* src = reinterpret_cast<const float4*>(W);
        float4* dst = reinterpret_cast<float4*>(sW);
#pragma unroll
        for (int i = 0; i < 32; ++i) dst[threadIdx.x + i * 128] = __ldg(src + threadIdx.x + i * 128);
    }
    __syncthreads();
    const int f = threadIdx.x;
    const int R = blockIdx.x, m = R >> 7, o = R & 127;
    const float* wa = Wa + o * 256 + m * 128;
    float acc = 0.f;
#pragma unroll 16
    for (int op = 0; op < FD; ++op) acc += __ldg(wa + op) * sW[op * FD + f];
    g_U[R * FD + f] = acc;
}

// ---------------------------------------------------------------------------
// nproj[n][o] = sum_f nodes[n][f] * W[o][f]   (fp32x2 FMA, exact)
// ---------------------------------------------------------------------------
#define PITCH 132
__device__ __forceinline__ void fma2(unsigned long long &d, unsigned long long a, unsigned long long b) {
    asm("fma.rn.f32x2 %0, %1, %2, %0;" : "+l"(d) : "l"(a), "l"(b));
}
__device__ __forceinline__ float hsum2(unsigned long long v) {
    float lo, hi;
    asm("mov.b64 {%0, %1}, %2;" : "=f"(lo), "=f"(hi) : "l"(v));
    return lo + hi;
}
__global__ __launch_bounds__(256, 2) void k_nproj(const float* __restrict__ nodes,
                                                  const float* __restrict__ W) {
    extern __shared__ float smf[];
    float* sW = smf;
    float* sRowBase = smf + FD * PITCH;
    for (int i = threadIdx.x; i < FD * FD; i += 256)
        sW[(i >> 7) * PITCH + (i & 127)] = W[i];
    __syncthreads();
    const int warp = threadIdx.x >> 5, lane = threadIdx.x & 31;
    float* sR = sRowBase + warp * 8 * FD;
    const int base = (blockIdx.x * 8 + warp) * 8;
    if (base >= NN) return;
#pragma unroll
    for (int r = 0; r < 8; ++r) {
        float4 v = reinterpret_cast<const float4*>(nodes + (size_t)(base + r) * FD)[lane];
        reinterpret_cast<float4*>(sR + r * FD)[lane] = v;
    }
    __syncwarp();
    const ulonglong2* up[4];
#pragma unroll
    for (int j = 0; j < 4; ++j)
        up[j] = reinterpret_cast<const ulonglong2*>(sW + (lane + 32 * j) * PITCH);
    unsigned long long acc[8][4];
#pragma unroll
    for (int r = 0; r < 8; ++r)
#pragma unroll
        for (int j = 0; j < 4; ++j) acc[r][j] = 0ull;
#pragma unroll 4
    for (int k4 = 0; k4 < 32; ++k4) {
        ulonglong2 u[4];
#pragma unroll
        for (int j = 0; j < 4; ++j) u[j] = up[j][k4];
#pragma unroll
        for (int r = 0; r < 8; ++r) {
            ulonglong2 a = reinterpret_cast<const ulonglong2*>(sR + r * FD)[k4];
#pragma unroll
            for (int j = 0; j < 4; ++j) { fma2(acc[r][j], a.x, u[j].x); fma2(acc[r][j], a.y, u[j].y); }
        }
    }
#pragma unroll
    for (int r = 0; r < 8; ++r)
#pragma unroll
        for (int j = 0; j < 4; ++j)
            g_nproj[(size_t)(base + r) * FD + lane + 32 * j] = hsum2(acc[r][j]);
}

// ---------------------------------------------------------------------------
// Main: persistent HMMA kernel, single fp16 term.
// Tile = 128 edges x 128 out, K=256 (neigh|asp). 16 warps: 4(M) x 4(N),
// warp tile 32x32. Double-buffered A chunks (K=64), register prefetch.
// ---------------------------------------------------------------------------
__global__ __launch_bounds__(512, 1) void k_main(
    const float* __restrict__ neighbors, const float* __restrict__ aspects,
    const float* __restrict__ att, const float* __restrict__ ba,
    const float* __restrict__ bias, float* __restrict__ out) {

    extern __shared__ __align__(16) char sm[];
    const int tid = threadIdx.x, lane = tid & 31, wid = tid >> 5;
    const int warp_m = wid >> 2, warp_n = wid & 3;
    const int m0 = warp_m * 32, n0 = warp_n * 32;
    const uint32_t smBase = smem_u32(sm);

    // ---- build resident B = fp16(U1|U2), K-major row per output col ----
    for (int idx = tid; idx < 8192; idx += 512) {
        float4 x = __ldg(reinterpret_cast<const float4*>(g_U) + idx);
        uint2 h = cvt4(x);
        const int f4 = idx & 31, o = (idx >> 5) & 127, m = idx >> 12;
        const int off = o * PB_BYTES + (m * 128 + f4 * 4) * 2;
        *reinterpret_cast<uint2*>(sm + SM_B + off) = h;
    }

    // ---- per-thread epilogue constants ----
    const int q = lane & 3, r = lane >> 2;
    float baR[8], biasR[8];
#pragma unroll
    for (int nt = 0; nt < 4; ++nt)
#pragma unroll
        for (int i = 0; i < 2; ++i) {
            const int col = n0 + nt * 8 + q * 2 + i;
            baR[nt * 2 + i]   = __ldg(ba + col);
            biasR[nt * 2 + i] = __ldg(bias + col);
        }
    __syncthreads();

    float acc[2][4][4];
#pragma unroll
    for (int mt = 0; mt < 2; ++mt)
#pragma unroll
        for (int nt = 0; nt < 4; ++nt)
#pragma unroll
            for (int i = 0; i < 4; ++i) acc[mt][nt][i] = 0.f;

    // ldmatrix lane base offsets
    const int lane15 = lane & 15, laneHi = lane >> 4;
    const uint32_t aRowOff = (uint32_t)((m0 + lane15) * PA_BYTES + laneHi * 16);
    const uint32_t bRow    = smBase + SM_B + (n0 + lane15) * PB_BYTES + laneHi * 16;

    const int grid = gridDim.x;
    float4 raw[4];
    int tile = blockIdx.x;
    if (tile < NTILES) {   // prologue: chunk 0 of first tile
        const float* src = neighbors + (size_t)tile * 16384 + (tid >> 4) * 128 + (tid & 15) * 4;
#pragma unroll
        for (int j = 0; j < 4; ++j)
            raw[j] = __ldg(reinterpret_cast<const float4*>(src + j * 4096));
    }

#pragma unroll 1
    for (; tile < NTILES; tile += grid) {
#pragma unroll 1
        for (int c = 0; c < 4; ++c) {
            const int stage = c & 1;
            // STS current chunk (fp32 -> fp16)
            {
                char* aP = sm + SM_A + stage * A_STAGE;
                const int mb = tid >> 4, sub = tid & 15;
#pragma unroll
                for (int j = 0; j < 4; ++j) {
                    uint2 h = cvt4(raw[j]);
                    const int row = mb + j * 32;
                    *reinterpret_cast<uint2*>(aP + row * PA_BYTES + sub * 8) = h;
                }
            }
            __syncthreads();
            // prefetch next chunk (or next tile's chunk 0)
            {
                int nc = c + 1, nt_ = tile;
                if (nc == 4) { nc = 0; nt_ = tile + grid; }
                if (nt_ < NTILES) {
                    const float* base = (nc < 2) ? neighbors : aspects;
                    const float* src = base + (size_t)nt_ * 16384 + (nc & 1) * 64
                                     + (tid >> 4) * 128 + (tid & 15) * 4;
#pragma unroll
                    for (int j = 0; j < 4; ++j)
                        raw[j] = __ldg(reinterpret_cast<const float4*>(src + j * 4096));
                }
            }
            // MMA on chunk c
            {
                const uint32_t aBase = smBase + SM_A + stage * A_STAGE + aRowOff;
                const uint32_t bC    = (uint32_t)(c * 128);   // k byte offset in B rows
#pragma unroll
                for (int ks = 0; ks < 4; ++ks) {
                    const uint32_t ko = ks * 32;
                    uint32_t ah[2][4], bh[2][4];
#pragma unroll
                    for (int mt = 0; mt < 2; ++mt) LDSM4(ah[mt], aBase + mt * (16 * PA_BYTES) + ko);
                    LDSM4(bh[0], bRow + bC + ko);
                    LDSM4(bh[1], bRow + 16 * PB_BYTES + bC + ko);
#pragma unroll
                    for (int mt = 0; mt < 2; ++mt)
#pragma unroll
                        for (int nt = 0; nt < 4; ++nt) {
                            const int g = nt >> 1, s = nt & 1;
                            MMA(acc[mt][nt], ah[mt], bh[g][s], bh[g][2 + s]);
                        }
                }
            }
            __syncthreads();
        }

        // ---- epilogue: leaky->exp->att-weight, reduce 16 edges/node, elu, store ----
#pragma unroll
        for (int mt = 0; mt < 2; ++mt) {
            const int edge0 = tile * 128 + m0 + mt * 16;
            const float attA = __ldg(att + edge0 + r);
            const float attB = __ldg(att + edge0 + 8 + r);
            const int node = edge0 >> 4;
            const float* np = g_nproj + (size_t)node * FD;
#pragma unroll
            for (int nt = 0; nt < 4; ++nt) {
                const int col0 = n0 + nt * 8 + q * 2;
                const float nb0 = __ldg(np + col0)     + baR[nt * 2];
                const float nb1 = __ldg(np + col0 + 1) + baR[nt * 2 + 1];
                float* a4 = acc[mt][nt];
                float v0 = a4[0] + nb0, v1 = a4[1] + nb1;
                float v2 = a4[2] + nb0, v3 = a4[3] + nb1;
                v0 = fmaxf(v0, 0.f) + NEG * fminf(v0, 0.f);
                v1 = fmaxf(v1, 0.f) + NEG * fminf(v1, 0.f);
                v2 = fmaxf(v2, 0.f) + NEG * fminf(v2, 0.f);
                v3 = fmaxf(v3, 0.f) + NEG * fminf(v3, 0.f);
                float s0 = attA * __expf(v0) + attB * __expf(v2);
                float s1 = attA * __expf(v1) + attB * __expf(v3);
                s0 += __shfl_xor_sync(0xFFFFFFFFu, s0, 4);
                s1 += __shfl_xor_sync(0xFFFFFFFFu, s1, 4);
                s0 += __shfl_xor_sync(0xFFFFFFFFu, s0, 8);
                s1 += __shfl_xor_sync(0xFFFFFFFFu, s1, 8);
                s0 += __shfl_xor_sync(0xFFFFFFFFu, s0, 16);
                s1 += __shfl_xor_sync(0xFFFFFFFFu, s1, 16);
                if (r == 0) {
                    float x0 = s0 + biasR[nt * 2];
                    float x1 = s1 + biasR[nt * 2 + 1];
                    float2 o2;
                    o2.x = (x0 > 0.f) ? x0 : expm1f(x0);
                    o2.y = (x1 > 0.f) ? x1 : expm1f(x1);
                    *reinterpret_cast<float2*>(out + (size_t)node * FD + col0) = o2;
                }
                a4[0] = a4[1] = a4[2] = a4[3] = 0.f;
            }
        }
    }
}

// ---------------------------------------------------------------------------
extern "C" void kernel_launch(void* const* d_in, const int* in_sizes, int n_in,
                              void* d_out, int out_size) {
    const float* nodes     = (const float*)d_in[0];
    const float* neighbors = (const float*)d_in[1];
    const float* aspects   = (const float*)d_in[2];
    const float* att       = (const float*)d_in[3];
    const float* W         = (const float*)d_in[4];
    const float* Wa        = (const float*)d_in[5];
    const float* ba        = (const float*)d_in[6];
    const float* bias      = (const float*)d_in[7];
    float* out = (float*)d_out;

    int dev = 0, nsm = 148;
    cudaGetDevice(&dev);
    cudaDeviceGetAttribute(&nsm, cudaDevAttrMultiProcessorCount, dev);

    const int smem_u     = FD * FD * sizeof(float);                      // 65536
    const int smem_nproj = (FD * PITCH + 8 * 8 * FD) * sizeof(float);    // 100352
    cudaFuncSetAttribute(k_computeU, cudaFuncAttributeMaxDynamicSharedMemorySize, smem_u);
    cudaFuncSetAttribute(k_nproj,    cudaFuncAttributeMaxDynamicSharedMemorySize, smem_nproj);
    cudaFuncSetAttribute(k_main,     cudaFuncAttributeMaxDynamicSharedMemorySize, SMEM_MAIN);

    k_computeU<<<256, 128, smem_u>>>(W, Wa);
    k_nproj<<<512, 256, smem_nproj>>>(nodes, W);
    k_main<<<nsm, 512, SMEM_MAIN>>>(neighbors, aspects, att, ba, bias, out);
}